// round 13
// baseline (speedup 1.0000x reference)
#include <cuda_runtime.h>
#include <cstdint>

// HONU order-2 as triangular register-blocked GEMM.
//   U[j][n] = W[p(j,n)] (n>=j) else 0;  Y = X U;  out = rowsum(Y .* X) + b
// R13: 2 rows per lane (one ld.shared.v2.f32 feeds 4 independent FMA2
// chains per U load), 16 warps x 2-column pairs A={2C,2C+1}, B={62-2C..}:
// trips 2C+2 and 64-2C -> constant 66, balanced + warp-uniform. 256 CTAs
// x 512 threads = 4096 warps (43% occ). U in smem (uniform LDS.64),
// 16-way template specialization, pre-expanded U in global.

#define THREADS 512
#define XT 66                    // xs_T row stride (floats; even -> 8B align)

__device__ __align__(16) float A_g[64 * 64];

__global__ void expand_kernel(const float* __restrict__ W) {
    int i = blockIdx.x * 256 + threadIdx.x;            // 4096 elements
    if (i < 64 * 64) {
        int j = i >> 6, n = i & 63;
        float v = 0.0f;
        if (n >= j) v = W[j * 64 - ((j * (j - 1)) >> 1) + (n - j)];
        A_g[i] = v;
    }
}

__device__ __forceinline__ void fma2(uint64_t& d, uint64_t a, uint64_t b) {
    asm("fma.rn.f32x2 %0, %1, %2, %0;" : "+l"(d) : "l"(a), "l"(b));
}
__device__ __forceinline__ uint64_t lds_u64(unsigned addr) {   // uniform 8B
    uint64_t v;
    asm volatile("ld.shared.b64 %0, [%1];" : "=l"(v) : "r"(addr));
    return v;
}
__device__ __forceinline__ void lds_v2f32(float& a, float& b, unsigned addr) {
    asm volatile("ld.shared.v2.f32 {%0,%1}, [%2];" : "=f"(a), "=f"(b) : "r"(addr));
}
__device__ __forceinline__ uint64_t splat(float x) {
    uint64_t d;
    asm("mov.b64 %0, {%1,%1};" : "=l"(d) : "r"(__float_as_uint(x)));
    return d;
}
__device__ __forceinline__ float lo32(uint64_t v) {
    uint32_t r; asm("mov.b64 {%0,_}, %1;" : "=r"(r) : "l"(v));
    return __uint_as_float(r);
}
__device__ __forceinline__ float hi32(uint64_t v) {
    uint32_t r; asm("mov.b64 {_,%0}, %1;" : "=r"(r) : "l"(v));
    return __uint_as_float(r);
}

template <int C>
__device__ __forceinline__ void body(unsigned xtb, unsigned ub,
                                     float& p0, float& p1) {
    constexpr int colA  = 2 * C;
    constexpr int colB  = 62 - 2 * C;
    constexpr int tripA = 2 * C + 2;      // A: k <= colA+1
    constexpr int kmax  = 64 - 2 * C;     // B: k <= colB+1 (>= tripA)

    uint64_t a0 = 0, a1 = 0, b0 = 0, b1 = 0;   // rows {2l,2l+1} x blocks {A,B}
    #pragma unroll
    for (int k = 0; k < kmax; ++k) {
        float f0, f1;
        lds_v2f32(f0, f1, xtb + k * (XT * 4));       // rows 2l, 2l+1
        uint64_t x0 = splat(f0), x1 = splat(f1);
        if (k < tripA) {                              // compile-time pruned
            uint64_t u = lds_u64(ub + (k * 64 + colA) * 4);   // uniform 8B
            fma2(a0, u, x0);
            fma2(a1, u, x1);
        }
        uint64_t v = lds_u64(ub + (k * 64 + colB) * 4);
        fma2(b0, v, x0);
        fma2(b1, v, x1);
    }

    // epilogue: q(col).{x,y} = x[{2l,2l+1}][col]
    float q0x, q0y, q1x, q1y, q2x, q2y, q3x, q3y;
    lds_v2f32(q0x, q0y, xtb + (colA + 0) * (XT * 4));
    lds_v2f32(q1x, q1y, xtb + (colA + 1) * (XT * 4));
    lds_v2f32(q2x, q2y, xtb + (colB + 0) * (XT * 4));
    lds_v2f32(q3x, q3y, xtb + (colB + 1) * (XT * 4));

    p0 = lo32(a0) * q0x + hi32(a0) * q1x + lo32(b0) * q2x + hi32(b0) * q3x;
    p1 = lo32(a1) * q0y + hi32(a1) * q1y + lo32(b1) * q2y + hi32(b1) * q3y;
}

__global__ void __launch_bounds__(THREADS, 2) honu_kernel(
    const float* __restrict__ x, const float* __restrict__ bias,
    float* __restrict__ out)
{
    __shared__ __align__(16) float U_s[64 * 64];     // 16 KB
    __shared__ __align__(8)  float xs_T[64 * XT];    // 16.5 KB transposed
    __shared__ __align__(8)  float part[16][64];     // 4 KB

    const int tid  = threadIdx.x;
    const int wid  = tid >> 5;                       // column-pair C (uniform)
    const int lane = tid & 31;
    const int row0 = blockIdx.x * 64;

    // --- Copy pre-expanded U (1024 float4s, 2 per thread, linear)
    {
        const float4* Ag4 = reinterpret_cast<const float4*>(A_g);
        float4*       Us4 = reinterpret_cast<float4*>(U_s);
        Us4[tid]           = Ag4[tid];
        Us4[THREADS + tid] = Ag4[THREADS + tid];
    }
    // --- Stage 64x64 x tile transposed: xs_T[k][r] = x[row0+r][k]
    {
        const float4* xg4 = reinterpret_cast<const float4*>(x + (size_t)row0 * 64);
        #pragma unroll
        for (int it = 0; it < 2; ++it) {
            int i = it * THREADS + tid;              // 0..1023 float4s
            int r = i >> 4, c4 = i & 15;
            float4 v = xg4[i];
            xs_T[(4 * c4 + 0) * XT + r] = v.x;
            xs_T[(4 * c4 + 1) * XT + r] = v.y;
            xs_T[(4 * c4 + 2) * XT + r] = v.z;
            xs_T[(4 * c4 + 3) * XT + r] = v.w;
        }
    }
    __syncthreads();

    const unsigned xtb = (unsigned)__cvta_generic_to_shared(xs_T) + lane * 8;
    const unsigned ub  = (unsigned)__cvta_generic_to_shared(U_s);

    float p0, p1;
    switch (wid) {
        case 0:  body<0>(xtb, ub, p0, p1);  break;
        case 1:  body<1>(xtb, ub, p0, p1);  break;
        case 2:  body<2>(xtb, ub, p0, p1);  break;
        case 3:  body<3>(xtb, ub, p0, p1);  break;
        case 4:  body<4>(xtb, ub, p0, p1);  break;
        case 5:  body<5>(xtb, ub, p0, p1);  break;
        case 6:  body<6>(xtb, ub, p0, p1);  break;
        case 7:  body<7>(xtb, ub, p0, p1);  break;
        case 8:  body<8>(xtb, ub, p0, p1);  break;
        case 9:  body<9>(xtb, ub, p0, p1);  break;
        case 10: body<10>(xtb, ub, p0, p1); break;
        case 11: body<11>(xtb, ub, p0, p1); break;
        case 12: body<12>(xtb, ub, p0, p1); break;
        case 13: body<13>(xtb, ub, p0, p1); break;
        case 14: body<14>(xtb, ub, p0, p1); break;
        default: body<15>(xtb, ub, p0, p1); break;
    }

    // part[C][2l..2l+1] via 8B store (linear, conflict-free)
    {
        unsigned pa = (unsigned)__cvta_generic_to_shared(part) + wid * 256 + lane * 8;
        asm volatile("st.shared.v2.f32 [%0], {%1,%2};" :: "r"(pa), "f"(p0), "f"(p1));
    }
    __syncthreads();

    // --- Warps 0-1 combine the 16 partials per row
    if (wid < 2) {
        int r = wid * 32 + lane;
        float s = part[0][r];
        #pragma unroll
        for (int c = 1; c < 16; ++c) s += part[c][r];
        out[row0 + r] = s + __ldg(bias);
    }
}

extern "C" void kernel_launch(void* const* d_in, const int* in_sizes, int n_in,
                              void* d_out, int out_size) {
    const float* x = (const float*)d_in[0];   // (16384, 64) f32
    const float* W = (const float*)d_in[1];   // (2145,)  f32 (first 2080 used)
    const float* b = (const float*)d_in[2];   // (1,)     f32
    float*     out = (float*)d_out;           // (16384,) f32

    expand_kernel<<<16, 256>>>(W);

    const int blocks = out_size / 64;         // 256 CTAs x 512 threads
    honu_kernel<<<blocks, THREADS>>>(x, b, out);
}

// round 14
// speedup vs baseline: 1.3821x; 1.3821x over previous
#include <cuda_runtime.h>
#include <cstdint>

// HONU order-2 as triangular register-blocked GEMM, split-K edition.
//   U[j][n] = W[p(j,n)] (n>=j) else 0;  Y = X U;  out = rowsum(Y .* X) + b
// Warp = (column-pair C, k-half H): block A cols {4C..4C+3} half-trip 2C+2,
// block B cols {60-4C..63-4C} half-trip 32-2C -> 34 balanced iters/warp.
// Partial dots are linear in k -> 16 scalar partials per row, summed by
// warp 0. 512 CTAs x 512 threads = 8192 warps (86% occ). U in smem
// (uniform LDS.v2.b64), in-CTA expand, 16-way template specialization.

#define THREADS 512
#define XT 33                    // xs_T row stride (floats)

__device__ __forceinline__ void fma2(uint64_t& d, uint64_t a, uint64_t b) {
    asm("fma.rn.f32x2 %0, %1, %2, %0;" : "+l"(d) : "l"(a), "l"(b));
}
__device__ __forceinline__ void lds_v2u64(uint64_t& a, uint64_t& b, unsigned addr) {
    asm volatile("ld.shared.v2.b64 {%0,%1}, [%2];" : "=l"(a), "=l"(b) : "r"(addr));
}
__device__ __forceinline__ float lds32(unsigned addr) {
    float v;
    asm volatile("ld.shared.f32 %0, [%1];" : "=f"(v) : "r"(addr));
    return v;
}
__device__ __forceinline__ uint64_t splat(float x) {
    uint64_t d;
    asm("mov.b64 %0, {%1,%1};" : "=l"(d) : "r"(__float_as_uint(x)));
    return d;
}
__device__ __forceinline__ float lo32(uint64_t v) {
    uint32_t r; asm("mov.b64 {%0,_}, %1;" : "=r"(r) : "l"(v));
    return __uint_as_float(r);
}
__device__ __forceinline__ float hi32(uint64_t v) {
    uint32_t r; asm("mov.b64 {_,%0}, %1;" : "=r"(r) : "l"(v));
    return __uint_as_float(r);
}

template <int C, int H>
__device__ __forceinline__ float body(unsigned xtb, unsigned ub) {
    constexpr int colA = 4 * C;
    constexpr int colB = 60 - 4 * C;
    constexpr int hA   = 2 * C + 2;       // half-trip, block A
    constexpr int hB   = 32 - 2 * C;      // half-trip, block B
    constexpr int kA0  = H * hA;
    constexpr int kB0  = H * hB;

    uint64_t a0 = 0, a1 = 0, b0 = 0, b1 = 0;
    #pragma unroll
    for (int k = kA0; k < kA0 + hA; ++k) {
        uint64_t xk2 = splat(lds32(xtb + k * (XT * 4)));      // 32 rows: 1 wf
        uint64_t u0, u1;
        lds_v2u64(u0, u1, ub + (k * 64 + colA) * 4);          // uniform 16B
        fma2(a0, u0, xk2);
        fma2(a1, u1, xk2);
    }
    #pragma unroll
    for (int k = kB0; k < kB0 + hB; ++k) {
        uint64_t xk2 = splat(lds32(xtb + k * (XT * 4)));
        uint64_t v0, v1;
        lds_v2u64(v0, v1, ub + (k * 64 + colB) * 4);
        fma2(b0, v0, xk2);
        fma2(b1, v1, xk2);
    }

    // Partial dot with x columns (linear in k -> summable across H)
    float p = 0.0f;
    p = fmaf(lo32(a0), lds32(xtb + (colA + 0) * (XT * 4)), p);
    p = fmaf(hi32(a0), lds32(xtb + (colA + 1) * (XT * 4)), p);
    p = fmaf(lo32(a1), lds32(xtb + (colA + 2) * (XT * 4)), p);
    p = fmaf(hi32(a1), lds32(xtb + (colA + 3) * (XT * 4)), p);
    p = fmaf(lo32(b0), lds32(xtb + (colB + 0) * (XT * 4)), p);
    p = fmaf(hi32(b0), lds32(xtb + (colB + 1) * (XT * 4)), p);
    p = fmaf(lo32(b1), lds32(xtb + (colB + 2) * (XT * 4)), p);
    p = fmaf(hi32(b1), lds32(xtb + (colB + 3) * (XT * 4)), p);
    return p;
}

__global__ void __launch_bounds__(THREADS, 4) honu_kernel(
    const float* __restrict__ x, const float* __restrict__ W,
    const float* __restrict__ bias, float* __restrict__ out)
{
    __shared__ __align__(16) float U_s[64 * 64];     // 16 KB
    __shared__ float xs_T[64 * XT];                  // 8.25 KB transposed
    __shared__ float part[16][32];                   // 2 KB

    const int tid  = threadIdx.x;
    const int wid  = tid >> 5;
    const int lane = tid & 31;
    const int row0 = blockIdx.x * 32;

    // --- Expand U from packed W in-CTA (8 elements/thread; W L2-resident)
    #pragma unroll
    for (int it = 0; it < 8; ++it) {
        int e = it * THREADS + tid;                  // 0..4095
        int j = e >> 6, n = e & 63;
        float v = 0.0f;
        if (n >= j) v = __ldg(&W[j * 64 - ((j * (j - 1)) >> 1) + (n - j)]);
        U_s[e] = v;
    }
    // --- Stage x tile transposed: xs_T[k][r] = x[row0+r][k] (1 float4/thread)
    {
        const float4* xg4 = reinterpret_cast<const float4*>(x + (size_t)row0 * 64);
        int r = tid >> 4, c4 = tid & 15;             // 512 float4s
        float4 v = xg4[tid];
        xs_T[(4 * c4 + 0) * XT + r] = v.x;
        xs_T[(4 * c4 + 1) * XT + r] = v.y;
        xs_T[(4 * c4 + 2) * XT + r] = v.z;
        xs_T[(4 * c4 + 3) * XT + r] = v.w;
    }
    __syncthreads();

    const unsigned xtb = (unsigned)__cvta_generic_to_shared(xs_T) + lane * 4;
    const unsigned ub  = (unsigned)__cvta_generic_to_shared(U_s);

    float p;
    switch (wid) {
        case 0:  p = body<0, 0>(xtb, ub); break;
        case 1:  p = body<0, 1>(xtb, ub); break;
        case 2:  p = body<1, 0>(xtb, ub); break;
        case 3:  p = body<1, 1>(xtb, ub); break;
        case 4:  p = body<2, 0>(xtb, ub); break;
        case 5:  p = body<2, 1>(xtb, ub); break;
        case 6:  p = body<3, 0>(xtb, ub); break;
        case 7:  p = body<3, 1>(xtb, ub); break;
        case 8:  p = body<4, 0>(xtb, ub); break;
        case 9:  p = body<4, 1>(xtb, ub); break;
        case 10: p = body<5, 0>(xtb, ub); break;
        case 11: p = body<5, 1>(xtb, ub); break;
        case 12: p = body<6, 0>(xtb, ub); break;
        case 13: p = body<6, 1>(xtb, ub); break;
        case 14: p = body<7, 0>(xtb, ub); break;
        default: p = body<7, 1>(xtb, ub); break;
    }

    part[wid][lane] = p;
    __syncthreads();

    // --- Warp 0 combines the 16 (C,H) partials per row
    if (wid == 0) {
        float s = part[0][lane];
        #pragma unroll
        for (int c = 1; c < 16; ++c) s += part[c][lane];
        out[row0 + lane] = s + __ldg(bias);
    }
}

extern "C" void kernel_launch(void* const* d_in, const int* in_sizes, int n_in,
                              void* d_out, int out_size) {
    const float* x = (const float*)d_in[0];   // (16384, 64) f32
    const float* W = (const float*)d_in[1];   // (2145,)  f32 (first 2080 used)
    const float* b = (const float*)d_in[2];   // (1,)     f32
    float*     out = (float*)d_out;           // (16384,) f32

    const int blocks = out_size / 32;         // 512 CTAs x 512 threads
    honu_kernel<<<blocks, THREADS>>>(x, W, b, out);
}